// round 14
// baseline (speedup 1.0000x reference)
#include <cuda_runtime.h>
#include <cstdint>

// Elementwise ReLU, HBM-bound. 2^27 fp32 = 1 GiB traffic.
//
// Axis evidence (per-thread f4 count -> kernel us / DRAM%):
//   grid-stride ~110 : ~164 / 78.5   (long-CTA spread penalty)
//   flat 1           : 156.8 / 82.0
//   flat 2           : 149.9 / 85.7
// Monotone improvement from amortizing per-CTA fixed cost over short CTAs.
// This round: flat 4 (32768 CTAs, 16KB/CTA, MLP_p1=4 front-batched loads).
// Load via __ldg, store evict-first (.cs) (established best policy).

__global__ __launch_bounds__(256, 8) void relu_flat4_kernel(
    const float4* __restrict__ in, float4* __restrict__ out, int n4)
{
    int base = blockIdx.x * (blockDim.x * 4) + threadIdx.x;
    int i0 = base;
    int i1 = base + blockDim.x;
    int i2 = base + 2 * blockDim.x;
    int i3 = base + 3 * blockDim.x;

    if (i3 < n4) {
        // Fast path: all four in-bounds (always true for this problem's shape).
        float4 a = __ldg(&in[i0]);
        float4 b = __ldg(&in[i1]);
        float4 c = __ldg(&in[i2]);
        float4 d = __ldg(&in[i3]);
        a.x = fmaxf(a.x, 0.f); a.y = fmaxf(a.y, 0.f); a.z = fmaxf(a.z, 0.f); a.w = fmaxf(a.w, 0.f);
        b.x = fmaxf(b.x, 0.f); b.y = fmaxf(b.y, 0.f); b.z = fmaxf(b.z, 0.f); b.w = fmaxf(b.w, 0.f);
        c.x = fmaxf(c.x, 0.f); c.y = fmaxf(c.y, 0.f); c.z = fmaxf(c.z, 0.f); c.w = fmaxf(c.w, 0.f);
        d.x = fmaxf(d.x, 0.f); d.y = fmaxf(d.y, 0.f); d.z = fmaxf(d.z, 0.f); d.w = fmaxf(d.w, 0.f);
        __stcs(&out[i0], a);
        __stcs(&out[i1], b);
        __stcs(&out[i2], c);
        __stcs(&out[i3], d);
    } else {
        #pragma unroll
        for (int k = 0; k < 4; k++) {
            int i = base + k * blockDim.x;
            if (i < n4) {
                float4 a = __ldg(&in[i]);
                a.x = fmaxf(a.x, 0.f); a.y = fmaxf(a.y, 0.f);
                a.z = fmaxf(a.z, 0.f); a.w = fmaxf(a.w, 0.f);
                __stcs(&out[i], a);
            }
        }
    }
}

__global__ __launch_bounds__(256) void relu_scalar_kernel(
    const float* __restrict__ in, float* __restrict__ out, int n, int start)
{
    int i = start + blockIdx.x * blockDim.x + threadIdx.x;
    if (i < n) out[i] = fmaxf(__ldg(&in[i]), 0.f);
}

extern "C" void kernel_launch(void* const* d_in, const int* in_sizes, int n_in,
                              void* d_out, int out_size)
{
    const float* in = (const float*)d_in[0];
    float* out = (float*)d_out;
    int n = in_sizes[0];

    int n4 = n / 4;          // 2^25 here
    if (n4 > 0) {
        const int threads = 256;
        const int per_cta = threads * 4;
        int blocks = (n4 + per_cta - 1) / per_cta;   // 32768
        relu_flat4_kernel<<<blocks, threads>>>(
            (const float4*)in, (float4*)out, n4);
    }
    int rem = n - n4 * 4;
    if (rem > 0) {
        relu_scalar_kernel<<<(rem + 255) / 256, 256>>>(in, out, n, n4 * 4);
    }
}